// round 3
// baseline (speedup 1.0000x reference)
#include <cuda_runtime.h>

// LWTA over groups of 4 consecutive fp32. Pure HBM-streaming kernel.
// R3: 8 float4 groups per thread (MLP=8), no bounds checks (exact tiling),
// streaming cache hints (__ldcs/__stcs) since every byte is touched once.

#define GPT 8  // groups (float4) per thread

__global__ void __launch_bounds__(256) lwta_kernel(const float4* __restrict__ in,
                                                   float4* __restrict__ out) {
    int base = blockIdx.x * (256 * GPT) + threadIdx.x;

    float4 v[GPT];

    // Front-batched independent streaming loads -> MLP = 8
#pragma unroll
    for (int k = 0; k < GPT; k++) {
        v[k] = __ldcs(&in[base + k * 256]);
    }

#pragma unroll
    for (int k = 0; k < GPT; k++) {
        float4 x = v[k];
        // argmax with first-max-wins (strict >), matching jnp.argmax
        float m = x.x;
        int w = 0;
        if (x.y > m) { m = x.y; w = 1; }
        if (x.z > m) { m = x.z; w = 2; }
        if (x.w > m) { m = x.w; w = 3; }
        float4 r;
        r.x = (w == 0) ? x.x : 0.0f;
        r.y = (w == 1) ? x.y : 0.0f;
        r.z = (w == 2) ? x.z : 0.0f;
        r.w = (w == 3) ? x.w : 0.0f;
        v[k] = r;
    }

#pragma unroll
    for (int k = 0; k < GPT; k++) {
        __stcs(&out[base + k * 256], v[k]);
    }
}

extern "C" void kernel_launch(void* const* d_in, const int* in_sizes, int n_in,
                              void* d_out, int out_size) {
    const float4* in = (const float4*)d_in[0];
    float4* out = (float4*)d_out;
    int n_elems = in_sizes[0];              // 4096*8192 = 33554432
    int n_groups = n_elems / 4;             // 8388608 float4 groups

    const int threads = 256;
    int groups_per_block = threads * GPT;   // 2048
    int blocks = n_groups / groups_per_block;  // 4096, exact
    lwta_kernel<<<blocks, threads>>>(in, out);
}

// round 5
// speedup vs baseline: 1.0625x; 1.0625x over previous
#include <cuda_runtime.h>

// LWTA over groups of 4 consecutive fp32. Pure HBM-streaming kernel.
// R4: back to MLP=4 (R3 showed MLP=8 overloads the L1tex wavefront queue and
// triggers cross-CTA spread), exact tiling (no guards -> [R+imm] addressing),
// plain cache ops, 512-thread blocks for warp-level (not per-thread) MLP.

#define GPT 4        // float4 groups per thread
#define NT  512      // threads per block

__global__ void __launch_bounds__(NT) lwta_kernel(const float4* __restrict__ in,
                                                  float4* __restrict__ out) {
    int base = blockIdx.x * (NT * GPT) + threadIdx.x;

    float4 v[GPT];

    // 4 independent coalesced loads, constant immediate offsets
#pragma unroll
    for (int k = 0; k < GPT; k++) {
        v[k] = in[base + k * NT];
    }

#pragma unroll
    for (int k = 0; k < GPT; k++) {
        float4 x = v[k];
        // argmax, first-max-wins (strict >), matching jnp.argmax
        float m = x.x;
        int w = 0;
        if (x.y > m) { m = x.y; w = 1; }
        if (x.z > m) { m = x.z; w = 2; }
        if (x.w > m) { m = x.w; w = 3; }
        float4 r;
        r.x = (w == 0) ? x.x : 0.0f;
        r.y = (w == 1) ? x.y : 0.0f;
        r.z = (w == 2) ? x.z : 0.0f;
        r.w = (w == 3) ? x.w : 0.0f;
        v[k] = r;
    }

#pragma unroll
    for (int k = 0; k < GPT; k++) {
        out[base + k * NT] = v[k];
    }
}

extern "C" void kernel_launch(void* const* d_in, const int* in_sizes, int n_in,
                              void* d_out, int out_size) {
    const float4* in = (const float4*)d_in[0];
    float4* out = (float4*)d_out;
    int n_elems = in_sizes[0];                 // 4096*8192 = 33554432
    int n_groups = n_elems / 4;                // 8388608 float4 groups

    int groups_per_block = NT * GPT;           // 2048
    int blocks = n_groups / groups_per_block;  // 4096, exact
    lwta_kernel<<<blocks, NT>>>(in, out);
}